// round 5
// baseline (speedup 1.0000x reference)
#include <cuda_runtime.h>
#include <cuda_fp16.h>
#include <cuda_bf16.h>

// ---------------------------------------------------------------------------
// GridSample 3D, trilinear, zeros padding, align_corners=False
// input  [2, 32, 64, 64, 64] f32
// grid   [2, 96, 96, 96, 3]  f32
// output [2, 32, 96, 96, 96] f32
//
// R4: fp16 channels-last scratch (32 MiB). Voxel = 64B, so 4 lanes per
// location (8 channels each, LDG.128) -> 8 locations per warp. Halves both
// L1 wavefronts/output and amortized coord math vs R3. fp32 accumulate
// keeps elementwise error <= 1 fp16 ulp (~4.9e-4) since values>=0 and
// weights are convex.
// ---------------------------------------------------------------------------

#define NB   2
#define C    32
#define D    64
#define HH   64
#define W    64
#define S3   (D * HH * W)
#define DO   96
#define HO   96
#define WO   96

// channels-last fp16 scratch: [NB][S3][C] = 32 MiB
static __device__ __half g_sch[(size_t)NB * S3 * C];

// ---------------------------------------------------------------------------
// K1: [n][c][s] -> [n][s][c] transpose with f32->f16 convert
// ---------------------------------------------------------------------------
__global__ void transpose_cl_kernel(const float* __restrict__ in) {
    __shared__ float tile[32][33];
    int bid   = blockIdx.x;
    int n     = bid >> 13;
    int sbase = (bid & 8191) << 5;
    int tx = threadIdx.x;
    int ty = threadIdx.y;

    const float* inp = in + (size_t)n * C * S3;
#pragma unroll
    for (int i = 0; i < 4; i++) {
        int c = ty + i * 8;
        tile[c][tx] = inp[(size_t)c * S3 + sbase + tx];
    }
    __syncthreads();
    __half* dst = g_sch + (size_t)n * S3 * C;
#pragma unroll
    for (int i = 0; i < 4; i++) {
        int s = ty + i * 8;
        dst[(size_t)(sbase + s) * C + tx] = __float2half_rn(tile[tx][s]);
    }
}

// ---------------------------------------------------------------------------
// K2: sampler. Block = 384 threads = one full 96-wide x-row.
// loc = tid>>2 (0..95), cq = tid&3 (8 channels = 16B per lane).
// Each corner gather: LDG.128 per lane; warp covers 8 locations.
// grid: NB*DO*HO = 18432 blocks.
// ---------------------------------------------------------------------------
__global__ __launch_bounds__(384, 4) void sample_kernel(
    const float* __restrict__ grid, float* __restrict__ out) {
    __shared__ float gsh[288];           // 96 locations * (x,y,z)
    __shared__ float tile[96 * 33];      // [x][chan], stride 33

    int bid = blockIdx.x;
    int yo  = bid % HO;  int t = bid / HO;
    int zo  = t % DO;
    int n   = t / DO;

    int tid = threadIdx.x;

    long gbase = (((long)n * DO + zo) * HO + yo) * (long)(WO * 3);
    if (tid < 288) gsh[tid] = grid[gbase + tid];
    __syncthreads();

    int loc = tid >> 2;      // output x in row
    int cq  = tid & 3;       // channel quarter (8 channels)

    float gx = gsh[3 * loc + 0];
    float gy = gsh[3 * loc + 1];
    float gz = gsh[3 * loc + 2];

    // align_corners=False: (g+1)*32 - 0.5
    float ix = (gx + 1.0f) * 32.0f - 0.5f;
    float iy = (gy + 1.0f) * 32.0f - 0.5f;
    float iz = (gz + 1.0f) * 32.0f - 0.5f;

    float fx = floorf(ix), fy = floorf(iy), fz = floorf(iz);
    float tx = ix - fx, ty = iy - fy, tz = iz - fz;
    int x0 = (int)fx, y0 = (int)fy, z0 = (int)fz;
    int x1 = x0 + 1, y1 = y0 + 1, z1 = z0 + 1;

    float wx0 = (x0 >= 0 && x0 < W)  ? (1.0f - tx) : 0.0f;
    float wx1 = (x1 >= 0 && x1 < W)  ? tx          : 0.0f;
    float wy0 = (y0 >= 0 && y0 < HH) ? (1.0f - ty) : 0.0f;
    float wy1 = (y1 >= 0 && y1 < HH) ? ty          : 0.0f;
    float wz0 = (z0 >= 0 && z0 < D)  ? (1.0f - tz) : 0.0f;
    float wz1 = (z1 >= 0 && z1 < D)  ? tz          : 0.0f;

    int xc0 = min(max(x0, 0), W - 1),  xc1 = min(max(x1, 0), W - 1);
    int yc0 = min(max(y0, 0), HH - 1), yc1 = min(max(y1, 0), HH - 1);
    int zc0 = min(max(z0, 0), D - 1),  zc1 = min(max(z1, 0), D - 1);

    const __half* p = g_sch +
        ((((size_t)n * D + zc0) * HH + yc0) * W + xc0) * C + cq * 8;
    int ox = (xc1 - xc0) * C;              // halves: 0 or 32
    int oy = (yc1 - yc0) * (W * C);
    int oz = (zc1 - zc0) * (HH * W * C);

    float w00 = wz0 * wy0, w01 = wz0 * wy1;
    float w10 = wz1 * wy0, w11 = wz1 * wy1;
    float w000 = w00 * wx0, w001 = w00 * wx1;
    float w010 = w01 * wx0, w011 = w01 * wx1;
    float w100 = w10 * wx0, w101 = w10 * wx1;
    float w110 = w11 * wx0, w111 = w11 * wx1;

    float acc[8];
#pragma unroll
    for (int j = 0; j < 8; j++) acc[j] = 0.0f;

#define CORNER(OFF, WW) { \
    uint4 r = *reinterpret_cast<const uint4*>(p + (OFF)); \
    float2 f0 = __half22float2(*reinterpret_cast<__half2*>(&r.x)); \
    float2 f1 = __half22float2(*reinterpret_cast<__half2*>(&r.y)); \
    float2 f2 = __half22float2(*reinterpret_cast<__half2*>(&r.z)); \
    float2 f3 = __half22float2(*reinterpret_cast<__half2*>(&r.w)); \
    acc[0] += (WW) * f0.x; acc[1] += (WW) * f0.y; \
    acc[2] += (WW) * f1.x; acc[3] += (WW) * f1.y; \
    acc[4] += (WW) * f2.x; acc[5] += (WW) * f2.y; \
    acc[6] += (WW) * f3.x; acc[7] += (WW) * f3.y; }

    CORNER(0,            w000)
    CORNER(ox,           w001)
    CORNER(oy,           w010)
    CORNER(oy + ox,      w011)
    CORNER(oz,           w100)
    CORNER(oz + ox,      w101)
    CORNER(oz + oy,      w110)
    CORNER(oz + oy + ox, w111)
#undef CORNER

    // stage: tile[loc][cq*8 + j]; bank (loc + 8*cq + j) mod 32 distinct/warp
    int row = loc * 33 + cq * 8;
#pragma unroll
    for (int j = 0; j < 8; j++) tile[row + j] = acc[j];
    __syncthreads();

    // coalesced writes: 3072 words, 8 per thread; each warp = 32 consecutive
    // x within one channel plane (96 = 3*32)
#pragma unroll
    for (int i = 0; i < 8; i++) {
        int idx = tid + i * 384;
        int c   = idx / 96;
        int x   = idx - c * 96;
        out[(((size_t)(n * C + c) * DO + zo) * HO + yo) * WO + x] =
            tile[x * 33 + c];
    }
}

extern "C" void kernel_launch(void* const* d_in, const int* in_sizes, int n_in,
                              void* d_out, int out_size) {
    const float* input = (const float*)d_in[0];
    const float* grid  = (const float*)d_in[1];
    float* out = (float*)d_out;

    transpose_cl_kernel<<<NB * (S3 / 32), dim3(32, 8)>>>(input);
    sample_kernel<<<NB * DO * HO, 384>>>(grid, out);
}